// round 12
// baseline (speedup 1.0000x reference)
#include <cuda_runtime.h>
#include <math.h>

#define BH 32
#define NTOK 4096
#define EH 64
#define MF 128
#define DM 512
#define NCH 16
#define IST 132
#define FST 132
#define DST 132

#define SQRT_TEMP 0.35355339059327373f
#define TEMPF 0.125f
#define HALF_LOG_M 2.4260151319598084f
#define LN2F 0.6931471805599453f

typedef unsigned long long u64t;
__device__ __forceinline__ u64t splat2(float x) {
    u64t r; asm("mov.b64 %0, {%1, %1};" : "=l"(r) : "f"(x)); return r;
}
__device__ __forceinline__ u64t pack2(float x, float y) {
    u64t r; asm("mov.b64 %0, {%1, %2};" : "=l"(r) : "f"(x), "f"(y)); return r;
}
__device__ __forceinline__ void fma2(u64t& c, u64t a, u64t b) {
    asm("fma.rn.f32x2 %0, %1, %2, %0;" : "+l"(c) : "l"(a), "l"(b));
}
__device__ __forceinline__ float2 unpk(u64t v) {
    float2 f; asm("mov.b64 {%0, %1}, %2;" : "=f"(f.x), "=f"(f.y) : "l"(v)); return f;
}

// ---------------- scratch ----------------
__device__ float g_qn2[BH*NTOK];
__device__ float g_kn2[BH*NTOK];
__device__ float g_MQ2[BH];
__device__ float g_MK2[BH];
__device__ float g_hashq[2*BH*NTOK];
__device__ float g_hashk[2*BH*NTOK];
__device__ int   g_qpos[2*BH*NTOK];
__device__ int   g_kpos[2*BH*NTOK];
__device__ int   g_qrev[2*BH*NTOK];
__device__ int   g_krev[2*BH*NTOK];
__device__ float g_qp[(size_t)BH*NTOK*MF];
__device__ float g_kp[(size_t)BH*NTOK*MF];    // log-phi (pre-exp)
__device__ float g_qls[BH*NTOK];
__device__ float g_krm[BH*NTOK];
__device__ float g_kls[BH];
__device__ float g_kvp[(size_t)NCH*BH*MF*EH];
__device__ float g_ksp[NCH*BH*MF];
__device__ float g_kv[BH*MF*EH];
__device__ float g_ksum[BH*MF];
__device__ float g_qk1[BH*NTOK];
__device__ float g_qkv[(size_t)BH*NTOK*EH];
__device__ float g_ob[(size_t)2*BH*NTOK*EH];
__device__ float g_lseb[2*BH*NTOK];
__device__ float g_dsb[2*BH*NTOK];
__device__ float4 g_msc[BH*NTOK];

// ---------------- K1: row squared norms (no copy) ----------------
__global__ __launch_bounds__(256) void k_norm(const float* __restrict__ query,
                                              const float* __restrict__ key) {
    int tid = threadIdx.x;
    int tl = tid >> 6, e = tid & 63;
    int t = blockIdx.x*4 + tl, bh = blockIdx.y;
    int b = bh >> 3, hh = bh & 7;
    size_t gi = ((size_t)(b*NTOK + t))*DM + hh*EH + e;
    float qv = query[gi], kv = key[gi];
    float q2 = qv*qv, k2 = kv*kv;
    #pragma unroll
    for (int o = 16; o; o >>= 1) {
        q2 += __shfl_down_sync(0xffffffffu, q2, o);
        k2 += __shfl_down_sync(0xffffffffu, k2, o);
    }
    __shared__ float sq[8], sk[8];
    if ((tid & 31) == 0) { sq[tid>>5] = q2; sk[tid>>5] = k2; }
    __syncthreads();
    if (e == 0) {
        g_qn2[bh*NTOK + t] = sq[2*tl] + sq[2*tl+1];
        g_kn2[bh*NTOK + t] = sk[2*tl] + sk[2*tl+1];
    }
}

// ---------------- K2: per-bh max squared norms ----------------
__global__ void k_maxn() {
    int bh = blockIdx.x, tid = threadIdx.x;
    float mq = 0.f, mk = 0.f;
    for (int i = tid; i < NTOK; i += 256) {
        mq = fmaxf(mq, g_qn2[bh*NTOK + i]);
        mk = fmaxf(mk, g_kn2[bh*NTOK + i]);
    }
    #pragma unroll
    for (int o = 16; o; o >>= 1) {
        mq = fmaxf(mq, __shfl_xor_sync(0xffffffffu, mq, o));
        mk = fmaxf(mk, __shfl_xor_sync(0xffffffffu, mk, o));
    }
    __shared__ float sq[8], sk[8];
    if ((tid & 31) == 0) { sq[tid>>5] = mq; sk[tid>>5] = mk; }
    __syncthreads();
    if (tid == 0) {
        float a = sq[0], b = sk[0];
        for (int w = 1; w < 8; w++) { a = fmaxf(a, sq[w]); b = fmaxf(b, sk[w]); }
        g_MQ2[bh] = a; g_MK2[bh] = b;
    }
}

// ---------------- K3: LSH hashes ----------------
__global__ void k_hash(const float* __restrict__ query, const float* __restrict__ key,
                       const float* __restrict__ alpha, const float* __restrict__ beta) {
    __shared__ float sal[2*(EH+2)];
    __shared__ float sbe[2];
    int bh = blockIdx.y;
    int tid = threadIdx.x;
    if (tid < 2*(EH+2)) sal[tid] = alpha[tid];
    if (tid < 2) sbe[tid] = beta[tid];
    __syncthreads();
    int t = blockIdx.x*256 + tid;
    int b = bh >> 3, hh = bh & 7;
    const float* qr = query + ((size_t)(b*NTOK + t))*DM + hh*EH;
    const float* kr = key   + ((size_t)(b*NTOK + t))*DM + hh*EH;
    float a0 = 0.f, a1 = 0.f, c0 = 0.f, c1 = 0.f;
    #pragma unroll 8
    for (int e = 0; e < EH; e++) {
        float al0 = sal[e*2], al1 = sal[e*2+1];
        float qe = qr[e], ke = kr[e];
        a0 += qe*al0; a1 += qe*al1;
        c0 += ke*al0; c1 += ke*al1;
    }
    float S = g_MQ2[bh] + g_MK2[bh];
    float extq = sqrtf(fmaxf(S - g_qn2[bh*NTOK + t], 0.f));
    float extk = sqrtf(fmaxf(S - g_kn2[bh*NTOK + t], 0.f));
    g_hashq[bh*NTOK + t]           = a0 + extq*sal[EH*2]       + sbe[0];
    g_hashq[BH*NTOK + bh*NTOK + t] = a1 + extq*sal[EH*2+1]     + sbe[1];
    g_hashk[bh*NTOK + t]           = c0 + extk*sal[(EH+1)*2]   + sbe[0];
    g_hashk[BH*NTOK + bh*NTOK + t] = c1 + extk*sal[(EH+1)*2+1] + sbe[1];
}

// ---------------- K5: performer feature maps as tiled GEMM ----------------
#define FEATG_SMEM (2*64*FST*4 + 128*4)
__global__ __launch_bounds__(256, 2) void k_featg(const float* __restrict__ query,
                                                  const float* __restrict__ key,
                                                  const float* __restrict__ W) {
    extern __shared__ float sm[];
    float* sXt = sm;                    // [64][FST]
    float* sWt = sm + 64*FST;           // [64][FST]
    float* sN  = sm + 2*64*FST;         // [128]
    int nb = blockIdx.x, bh = blockIdx.y, isK = blockIdx.z;
    int tid = threadIdx.x, tx = tid & 15, ty = tid >> 4;
    int b = bh >> 3, hh = bh & 7;
    const float* X  = isK ? key : query;
    const float* n2 = isK ? g_kn2 : g_qn2;
    size_t xbase = ((size_t)b*NTOK)*DM + hh*EH;
    int tb = nb*128;
    for (int idx = tid; idx < 8192; idx += 256) {
        int i = idx >> 6, e = idx & 63;
        sXt[e*FST + i] = X[xbase + (size_t)(tb + i)*DM + e];
        sWt[e*FST + i] = W[i*EH + e];
    }
    if (tid < 128) sN[tid] = n2[bh*NTOK + tb + tid];
    __syncthreads();
    u64t acc[4][8];
    #pragma unroll
    for (int r = 0; r < 4; r++)
        #pragma unroll
        for (int c = 0; c < 8; c++) acc[r][c] = 0ull;
    #pragma unroll 2
    for (int e = 0; e < 64; e++) {
        const u64t* ap = (const u64t*)(sXt + e*FST + ty*8);
        float4 b0q = *(const float4*)(sWt + e*FST + tx*8);
        float4 b1q = *(const float4*)(sWt + e*FST + tx*8 + 4);
        u64t bs[8];
        bs[0]=splat2(b0q.x); bs[1]=splat2(b0q.y); bs[2]=splat2(b0q.z); bs[3]=splat2(b0q.w);
        bs[4]=splat2(b1q.x); bs[5]=splat2(b1q.y); bs[6]=splat2(b1q.z); bs[7]=splat2(b1q.w);
        #pragma unroll
        for (int r2 = 0; r2 < 4; r2++) {
            u64t av = ap[r2];
            #pragma unroll
            for (int c = 0; c < 8; c++) fma2(acc[r2][c], av, bs[c]);
        }
    }
    #pragma unroll
    for (int r2 = 0; r2 < 4; r2++) {
        float2 v[8];
        #pragma unroll
        for (int c = 0; c < 8; c++) v[c] = unpk(acc[r2][c]);
        #pragma unroll
        for (int half = 0; half < 2; half++) {
            int row = ty*8 + r2*2 + half;
            int t = tb + row;
            float nn = 0.5f*TEMPF*sN[row] + HALF_LOG_M;
            float lp[8];
            float rm = -1e30f;
            #pragma unroll
            for (int c = 0; c < 8; c++) {
                lp[c] = (half ? v[c].y : v[c].x)*SQRT_TEMP - nn;
                rm = fmaxf(rm, lp[c]);
            }
            #pragma unroll
            for (int off = 8; off; off >>= 1) rm = fmaxf(rm, __shfl_xor_sync(0xffffffffu, rm, off));
            size_t base = ((size_t)bh*NTOK + t)*MF + tx*8;
            if (!isK) {
                *(float4*)(g_qp + base) = make_float4(__expf(lp[0]-rm), __expf(lp[1]-rm),
                                                      __expf(lp[2]-rm), __expf(lp[3]-rm));
                *(float4*)(g_qp + base + 4) = make_float4(__expf(lp[4]-rm), __expf(lp[5]-rm),
                                                          __expf(lp[6]-rm), __expf(lp[7]-rm));
                if (tx == 0) g_qls[bh*NTOK + t] = rm;
            } else {
                *(float4*)(g_kp + base)     = make_float4(lp[0], lp[1], lp[2], lp[3]);
                *(float4*)(g_kp + base + 4) = make_float4(lp[4], lp[5], lp[6], lp[7]);
                if (tx == 0) g_krm[bh*NTOK + t] = rm;
            }
        }
    }
}

// ---------------- K4: stable bitonic argsort ----------------
__global__ void k_sort() {
    __shared__ float sv[NTOK];
    __shared__ int   si[NTOK];
    int which = blockIdx.x >> 6;
    int rem   = blockIdx.x & 63;
    const float* src = which ? (g_hashk + (size_t)rem*NTOK) : (g_hashq + (size_t)rem*NTOK);
    int tid = threadIdx.x;
    for (int i = tid; i < NTOK; i += 512) { sv[i] = src[i]; si[i] = i; }
    __syncthreads();
    for (int k = 2; k <= NTOK; k <<= 1)
        for (int j = k >> 1; j > 0; j >>= 1) {
            for (int p = tid; p < NTOK/2; p += 512) {
                int i  = ((p & ~(j-1)) << 1) | (p & (j-1));
                int ix = i | j;
                bool up = ((i & k) == 0);
                float vi = sv[i], vj = sv[ix];
                int ii = si[i], ij = si[ix];
                bool agt = (vi > vj) || (vi == vj && ii > ij);
                if (agt == up) { sv[i] = vj; sv[ix] = vi; si[i] = ij; si[ix] = ii; }
            }
            __syncthreads();
        }
    int* pos = which ? g_kpos : g_qpos;
    int* rev = which ? g_krev : g_qrev;
    for (int r = tid; r < NTOK; r += 512) {
        int idx = si[r];
        pos[rem*NTOK + r]   = idx;
        rev[rem*NTOK + idx] = r;
    }
}

// ---------------- K6: per-bh max of k log-phi ----------------
__global__ void k_kls() {
    int bh = blockIdx.x, tid = threadIdx.x;
    float m = -1e30f;
    for (int i = tid; i < NTOK; i += 256) m = fmaxf(m, g_krm[bh*NTOK + i]);
    #pragma unroll
    for (int o = 16; o; o >>= 1) m = fmaxf(m, __shfl_xor_sync(0xffffffffu, m, o));
    __shared__ float s[8];
    if ((tid & 31) == 0) s[tid>>5] = m;
    __syncthreads();
    if (tid == 0) {
        float r = s[0];
        for (int w = 1; w < 8; w++) r = fmaxf(r, s[w]);
        g_kls[bh] = r;
    }
}

// ---------------- K8: partial kv = exp(k')^T v (2 tiles per block) ----------------
#define KVP_SMEM (128*IST*4 + 128*68*4)
__global__ __launch_bounds__(256, 2) void k_kvpart2(const float* __restrict__ value) {
    extern __shared__ float sm[];
    float* sKP = sm;                    // [128 t][IST]
    float* sV  = sm + 128*IST;          // [128 t][68]
    int ch = blockIdx.x, bh = blockIdx.y;
    int tid = threadIdx.x, tx = tid & 15, ty = tid >> 4;
    int b = bh >> 3, hh = bh & 7;
    size_t vbase = ((size_t)b*NTOK)*DM + hh*EH;
    float kls = g_kls[bh];
    u64t acc[4][4];
    #pragma unroll
    for (int r = 0; r < 4; r++)
        #pragma unroll
        for (int c = 0; c < 4; c++) acc[r][c] = 0ull;
    float csum = 0.f;
    for (int tile = 0; tile < 2; tile++) {
        int t0 = ch*256 + tile*128;
        __syncthreads();
        for (int idx = tid; idx < 16384; idx += 256) {
            int t = idx >> 7, m = idx & 127;
            sKP[t*IST + m] = __expf(g_kp[((size_t)bh*NTOK + t0 + t)*MF + m] - kls);
        }
        for (int idx = tid; idx < 8192; idx += 256) {
            int t = idx >> 6, d = idx & 63;
            sV[t*68 + d] = value[vbase + (size_t)(t0 + t)*DM + d];
        }
        __syncthreads();
        #pragma unroll 4
        for (int t = 0; t < 128; t++) {
            const u64t* ap = (const u64t*)(sKP + t*IST + ty*8);
            float4 bq = *(const float4*)(sV + t*68 + tx*4);
            u64t b0 = splat2(bq.x), b1 = splat2(bq.y), b2 = splat2(bq.z), b3 = splat2(bq.w);
            #pragma unroll
            for (int r2 = 0; r2 < 4; r2++) {
                u64t av = ap[r2];
                fma2(acc[r2][0], av, b0); fma2(acc[r2][1], av, b1);
                fma2(acc[r2][2], av, b2); fma2(acc[r2][3], av, b3);
            }
        }
        if (tid < 128) {
            float s = 0.f;
            #pragma unroll 8
            for (int t = 0; t < 128; t++) s += sKP[t*IST + tid];
            csum += s;
        }
    }
    float* dst = g_kvp + ((size_t)(ch*BH + bh))*MF*EH;
    #pragma unroll
    for (int r2 = 0; r2 < 4; r2++) {
        float2 v0 = unpk(acc[r2][0]), v1 = unpk(acc[r2][1]);
        float2 v2 = unpk(acc[r2][2]), v3 = unpk(acc[r2][3]);
        int m = ty*8 + r2*2;
        *(float4*)(dst + (size_t)m*EH + tx*4)     = make_float4(v0.x, v1.x, v2.x, v3.x);
        *(float4*)(dst + (size_t)(m+1)*EH + tx*4) = make_float4(v0.y, v1.y, v2.y, v3.y);
    }
    if (tid < 128) g_ksp[(ch*BH + bh)*MF + tid] = csum;
}

// ---------------- K8b: deterministic reduce ----------------
__global__ void k_kvred() {
    int idx = blockIdx.x*256 + threadIdx.x;
    float s = 0.f;
    #pragma unroll
    for (int c = 0; c < NCH; c++) s += g_kvp[(size_t)c*BH*MF*EH + idx];
    g_kv[idx] = s;
    if (idx < BH*MF) {
        float ss = 0.f;
        #pragma unroll
        for (int c = 0; c < NCH; c++) ss += g_ksp[c*BH*MF + idx];
        g_ksum[idx] = ss;
    }
}

// ---------------- K9: qkv = q' kv + qk1, tiled GEMM ----------------
#define QKV_SMEM (128*IST*4 + 128*68*4 + 128*4)
__global__ __launch_bounds__(256, 2) void k_qkv2() {
    extern __shared__ float sm[];
    float* sQPt = sm;                   // [128 m][IST tokens]
    float* sKV  = sm + 128*IST;         // [128 m][68]
    float* sks  = sm + 128*IST + 128*68;
    int nb = blockIdx.x, bh = blockIdx.y;
    int tid = threadIdx.x, tx = tid & 15, ty = tid >> 4;
    int tb = nb*128;
    for (int idx = tid; idx < 16384; idx += 256) {
        int i = idx >> 7, m = idx & 127;
        sQPt[m*IST + i] = g_qp[((size_t)bh*NTOK + tb + i)*MF + m];
    }
    for (int idx = tid; idx < 8192; idx += 256) {
        int m = idx >> 6, d = idx & 63;
        sKV[m*68 + d] = g_kv[(size_t)bh*MF*EH + m*EH + d];
    }
    if (tid < 128) sks[tid] = g_ksum[bh*MF + tid];
    __syncthreads();
    u64t acc[4][4];
    #pragma unroll
    for (int r = 0; r < 4; r++)
        #pragma unroll
        for (int c = 0; c < 4; c++) acc[r][c] = 0ull;
    #pragma unroll 4
    for (int m = 0; m < 128; m++) {
        const u64t* ap = (const u64t*)(sQPt + m*IST + ty*8);
        float4 bq = *(const float4*)(sKV + m*68 + tx*4);
        u64t b0 = splat2(bq.x), b1 = splat2(bq.y), b2 = splat2(bq.z), b3 = splat2(bq.w);
        #pragma unroll
        for (int r2 = 0; r2 < 4; r2++) {
            u64t av = ap[r2];
            fma2(acc[r2][0], av, b0); fma2(acc[r2][1], av, b1);
            fma2(acc[r2][2], av, b2); fma2(acc[r2][3], av, b3);
        }
    }
    #pragma unroll
    for (int r2 = 0; r2 < 4; r2++) {
        float2 v0 = unpk(acc[r2][0]), v1 = unpk(acc[r2][1]);
        float2 v2 = unpk(acc[r2][2]), v3 = unpk(acc[r2][3]);
        int row = ty*8 + r2*2;
        *(float4*)(g_qkv + ((size_t)bh*NTOK + tb + row)*EH + tx*4)
            = make_float4(v0.x, v1.x, v2.x, v3.x);
        *(float4*)(g_qkv + ((size_t)bh*NTOK + tb + row + 1)*EH + tx*4)
            = make_float4(v0.y, v1.y, v2.y, v3.y);
    }
    if (tid < 128) {
        float s = 0.f;
        #pragma unroll 8
        for (int m = 0; m < 128; m++) s += sQPt[m*IST + tid]*sks[m];
        g_qk1[bh*NTOK + tb + tid] = s;
    }
}

// ======= K10: fully fused bucketed correction =======
#define R1_FLOATS 8704
#define BKT_SMEM ((128*DST + R1_FLOATS)*4)
__global__ __launch_bounds__(256, 2) void k_bucket2(const float* __restrict__ query,
                                                    const float* __restrict__ key,
                                                    const float* __restrict__ value) {
    extern __shared__ float sm[];
    float* sD  = sm;                    // [128][DST]
    float* sR1 = sm + 128*DST;          // tiles: [32][IST] x2 ; later V [128][68]
    __shared__ int sQi[128], sKi[128], sQb[128], sKb[128];
    __shared__ float sPls[128];
    int nb = blockIdx.x, bh = blockIdx.y, h = blockIdx.z;
    int tid = threadIdx.x, tx = tid & 15, ty = tid >> 4;
    int o = 1 - h;
    int b = bh >> 3, hh = bh & 7;
    size_t xbase = ((size_t)b*NTOK)*DM + hh*EH;
    float kls = g_kls[bh];
    if (tid < 128) {
        int qi = g_qpos[(h*BH + bh)*NTOK + nb*128 + tid];
        int ki = g_kpos[(h*BH + bh)*NTOK + nb*128 + tid];
        sQi[tid] = qi; sKi[tid] = ki;
        sQb[tid] = g_qrev[(o*BH + bh)*NTOK + qi] >> 7;
        sKb[tid] = g_krev[(o*BH + bh)*NTOK + ki] >> 7;
        sPls[tid] = g_qls[bh*NTOK + qi] + kls;
    }
    float* sQt = sR1;                   // [32][IST]
    float* sKt = sR1 + 32*IST;

    u64t aI[4][8];
    #pragma unroll
    for (int r = 0; r < 4; r++)
        #pragma unroll
        for (int c = 0; c < 8; c++) aI[r][c] = 0ull;
    for (int ec = 0; ec < 2; ec++) {
        __syncthreads();
        for (int idx = tid; idx < 4096; idx += 256) {
            int i = idx >> 5, el = idx & 31;
            sQt[el*IST + i] = query[xbase + (size_t)sQi[i]*DM + ec*32 + el];
            sKt[el*IST + i] = key[xbase + (size_t)sKi[i]*DM + ec*32 + el];
        }
        __syncthreads();
        #pragma unroll 2
        for (int e = 0; e < 32; e++) {
            const u64t* ap = (const u64t*)(sQt + e*IST + ty*8);
            float4 b0q = *(const float4*)(sKt + e*IST + tx*8);
            float4 b1q = *(const float4*)(sKt + e*IST + tx*8 + 4);
            u64t bs[8];
            bs[0]=splat2(b0q.x); bs[1]=splat2(b0q.y); bs[2]=splat2(b0q.z); bs[3]=splat2(b0q.w);
            bs[4]=splat2(b1q.x); bs[5]=splat2(b1q.y); bs[6]=splat2(b1q.z); bs[7]=splat2(b1q.w);
            #pragma unroll
            for (int r2 = 0; r2 < 4; r2++) {
                u64t av = ap[r2];
                #pragma unroll
                for (int c = 0; c < 8; c++) fma2(aI[r2][c], av, bs[c]);
            }
        }
    }
    #pragma unroll
    for (int r2 = 0; r2 < 4; r2++) {
        float2 v[8];
        #pragma unroll
        for (int c = 0; c < 8; c++) v[c] = unpk(aI[r2][c]);
        int row = ty*8 + r2*2;
        *(float4*)(sD + row*DST + tx*8)     = make_float4(v[0].x, v[1].x, v[2].x, v[3].x);
        *(float4*)(sD + row*DST + tx*8 + 4) = make_float4(v[4].x, v[5].x, v[6].x, v[7].x);
        *(float4*)(sD + (row+1)*DST + tx*8)     = make_float4(v[0].y, v[1].y, v[2].y, v[3].y);
        *(float4*)(sD + (row+1)*DST + tx*8 + 4) = make_float4(v[4].y, v[5].y, v[6].y, v[7].y);
    }

    u64t aP[4][8];
    #pragma unroll
    for (int r = 0; r < 4; r++)
        #pragma unroll
        for (int c = 0; c < 8; c++) aP[r][c] = 0ull;
    for (int mc = 0; mc < 4; mc++) {
        __syncthreads();
        for (int idx = tid; idx < 4096; idx += 256) {
            int i = idx >> 5, ml = idx & 31;
            sQt[ml*IST + i] = g_qp[((size_t)bh*NTOK + sQi[i])*MF + mc*32 + ml];
            sKt[ml*IST + i] = __expf(g_kp[((size_t)bh*NTOK + sKi[i])*MF + mc*32 + ml] - kls);
        }
        __syncthreads();
        #pragma unroll 2
        for (int m = 0; m < 32; m++) {
            const u64t* ap = (const u64t*)(sQt + m*IST + ty*8);
            float4 b0q = *(const float4*)(sKt + m*IST + tx*8);
            float4 b1q = *(const float4*)(sKt + m*IST + tx*8 + 4);
            u64t bs[8];
            bs[0]=splat2(b0q.x); bs[1]=splat2(b0q.y); bs[2]=splat2(b0q.z); bs[3]=splat2(b0q.w);
            bs[4]=splat2(b1q.x); bs[5]=splat2(b1q.y); bs[6]=splat2(b1q.z); bs[7]=splat2(b1q.w);
            #pragma unroll
            for (int r2 = 0; r2 < 4; r2++) {
                u64t av = ap[r2];
                #pragma unroll
                for (int c = 0; c < 8; c++) fma2(aP[r2][c], av, bs[c]);
            }
        }
    }
    __syncthreads();

    int kb[8];
    #pragma unroll
    for (int c = 0; c < 8; c++) kb[c] = sKb[tx*8 + c];
    #pragma unroll
    for (int r2 = 0; r2 < 4; r2++) {
        float2 P[8];
        #pragma unroll
        for (int c = 0; c < 8; c++) P[c] = unpk(aP[r2][c]);
        #pragma unroll
        for (int half = 0; half < 2; half++) {
            int row = ty*8 + r2*2 + half;
            int qb = sQb[row]; float pls = sPls[row];
            float4 in0 = *(const float4*)(sD + row*DST + tx*8);
            float4 in1 = *(const float4*)(sD + row*DST + tx*8 + 4);
            float iv[8] = {in0.x, in0.y, in0.z, in0.w, in1.x, in1.y, in1.z, in1.w};
            float pv[8];
            float rm = -1e30f;
            #pragma unroll
            for (int c = 0; c < 8; c++) {
                bool d2 = (qb == kb[c]);
                iv[c] = iv[c]*TEMPF - (d2 ? LN2F : 0.f);
                pv[c] = (half ? P[c].y : P[c].x) * (d2 ? 0.5f : 1.f);
                rm = fmaxf(rm, iv[c]);
            }
            #pragma unroll
            for (int off = 8; off; off >>= 1) rm = fmaxf(rm, __shfl_xor_sync(0xffffffffu, rm, off));
            float l = fmaxf(rm, pls);
            float pe = __expf(pls - l);
            float dv[8];
            float s = 0.f;
            #pragma unroll
            for (int c = 0; c < 8; c++) { dv[c] = __expf(iv[c] - l) - pv[c]*pe; s += dv[c]; }
            *(float4*)(sD + row*DST + tx*8)     = make_float4(dv[0], dv[1], dv[2], dv[3]);
            *(float4*)(sD + row*DST + tx*8 + 4) = make_float4(dv[4], dv[5], dv[6], dv[7]);
            #pragma unroll
            for (int off = 8; off; off >>= 1) s += __shfl_xor_sync(0xffffffffu, s, off);
            if (tx == 0) {
                int t = sQi[row];
                size_t bi = (size_t)(h*BH + bh)*NTOK + t;
                g_lseb[bi] = l;
                g_dsb[bi]  = s;
            }
        }
    }
    float* sV = sR1;                    // [128][68]
    for (int idx = tid; idx < 8192; idx += 256) {
        int i = idx >> 6, d = idx & 63;
        sV[i*68 + d] = value[xbase + (size_t)sKi[i]*DM + d];
    }
    __syncthreads();

    int tx2 = tid & 15, ty2 = tid >> 4;
    u64t accO[8][2];
    #pragma unroll
    for (int r = 0; r < 8; r++) { accO[r][0] = 0ull; accO[r][1] = 0ull; }
    for (int j0 = 0; j0 < 128; j0 += 4) {
        float4 a[8];
        #pragma unroll
        for (int r = 0; r < 8; r++) a[r] = *(const float4*)(sD + (ty2*8 + r)*DST + j0);
        #pragma unroll
        for (int jj = 0; jj < 4; jj++) {
            float4 t = *(const float4*)(sV + (j0 + jj)*68 + tx2*4);
            u64t bv0 = pack2(t.x, t.y), bv1 = pack2(t.z, t.w);
            #pragma unroll
            for (int r = 0; r < 8; r++) {
                float av = (jj==0)?a[r].x:(jj==1)?a[r].y:(jj==2)?a[r].z:a[r].w;
                u64t s = splat2(av);
                fma2(accO[r][0], s, bv0); fma2(accO[r][1], s, bv1);
            }
        }
    }
    #pragma unroll
    for (int r = 0; r < 8; r++) {
        int t = sQi[ty2*8 + r];
        float2 u0 = unpk(accO[r][0]), u1 = unpk(accO[r][1]);
        *(float4*)(g_ob + ((size_t)(h*BH + bh)*NTOK + t)*EH + tx2*4) =
            make_float4(u0.x, u0.y, u1.x, u1.y);
    }
}

// ---------------- K11: merge scalars per (bh, t) ----------------
__global__ void k_mscal() {
    int t = blockIdx.x*256 + threadIdx.x;
    int bh = blockIdx.y;
    size_t i0 = (size_t)bh*NTOK + t;
    size_t i1 = (size_t)(BH + bh)*NTOK + t;
    float l0 = g_lseb[i0], l1 = g_lseb[i1];
    float mx = fmaxf(l0, l1);
    float norm = mx + logf(__expf(l0 - mx) + __expf(l1 - mx));
    float p0 = __expf(l0 - norm), p1 = __expf(l1 - norm);
    float pls = g_qls[bh*NTOK + t] + g_kls[bh];
    float psc = __expf(pls - norm);
    float z = g_dsb[i0]*p0 + g_dsb[i1]*p1 + g_qk1[bh*NTOK + t]*psc;
    float invz = 1.f / fmaxf(z, 1e-6f);
    g_msc[i0] = make_float4(p0*invz, p1*invz, psc*invz, 0.f);
}

// ---------------- K12: final projection with fused merge ----------------
#define WS 130
#define XS 132
__global__ __launch_bounds__(256) void k_final(const float* __restrict__ Wf,
                                               const float* __restrict__ bias,
                                               float* __restrict__ out) {
    __shared__ float sW2[64*WS];
    __shared__ float sX[16*XS];
    int tid = threadIdx.x;
    int tok = tid >> 6, eo = tid & 63;
    int g0 = blockIdx.x*16;
    u64t acc2[4];
    #pragma unroll
    for (int tt = 0; tt < 4; tt++) acc2[tt] = 0ull;
    for (int c = 0; c < 4; c++) {
        __syncthreads();
        for (int idx = tid; idx < 8192; idx += 256) {
            int e2 = idx >> 7, hd = idx & 127;
            sW2[e2*WS + hd] = Wf[e2*512 + c*128 + hd];
        }
        for (int idx = tid; idx < 2048; idx += 256) {
            int tk = idx >> 7, hd = idx & 127;
            int gg = g0 + tk;
            int b = gg >> 12, t = gg & 4095;
            int hdg = c*128 + hd;
            int bh = b*8 + (hdg >> 6);
            int d = hdg & 63;
            size_t ti = (size_t)bh*NTOK + t;
            float4 ms = g_msc[ti];
            float val = g_ob[ti*EH + d]*ms.x
                      + g_ob[(size_t)BH*NTOK*EH + ti*EH + d]*ms.y
                      + g_qkv[ti*EH + d]*ms.z;
            sX[tk*XS + hd] = val;
        }
        __syncthreads();
        const u64t* wp = (const u64t*)(sW2 + eo*WS);
        #pragma unroll
        for (int tt = 0; tt < 4; tt++) {
            const float4* x4 = (const float4*)(sX + (tok + tt*4)*XS);
            #pragma unroll
            for (int h4 = 0; h4 < 32; h4++) {
                float4 xv = x4[h4];
                fma2(acc2[tt], pack2(xv.x, xv.y), wp[2*h4]);
                fma2(acc2[tt], pack2(xv.z, xv.w), wp[2*h4+1]);
            }
        }
    }
    float bv = bias[eo];
    #pragma unroll
    for (int tt = 0; tt < 4; tt++) {
        float2 u = unpk(acc2[tt]);
        out[(size_t)(g0 + tok + tt*4)*EH + eo] = u.x + u.y + bv;
    }
}

// ---------------- launch ----------------
extern "C" void kernel_launch(void* const* d_in, const int* in_sizes, int n_in,
                              void* d_out, int out_size) {
    const float* query = (const float*)d_in[0];
    const float* key   = (const float*)d_in[1];
    const float* value = (const float*)d_in[2];
    const float* projW = (const float*)d_in[3];
    const float* alpha = (const float*)d_in[4];
    const float* beta  = (const float*)d_in[5];
    const float* outW  = (const float*)d_in[6];
    const float* outb  = (const float*)d_in[7];
    float* out = (float*)d_out;

    cudaFuncSetAttribute(k_featg,   cudaFuncAttributeMaxDynamicSharedMemorySize, FEATG_SMEM);
    cudaFuncSetAttribute(k_kvpart2, cudaFuncAttributeMaxDynamicSharedMemorySize, KVP_SMEM);
    cudaFuncSetAttribute(k_qkv2,    cudaFuncAttributeMaxDynamicSharedMemorySize, QKV_SMEM);
    cudaFuncSetAttribute(k_bucket2, cudaFuncAttributeMaxDynamicSharedMemorySize, BKT_SMEM);

    k_norm<<<dim3(NTOK/4, BH), 256>>>(query, key);
    k_featg<<<dim3(NTOK/128, BH, 2), 256, FEATG_SMEM>>>(query, key, projW);
    k_kls<<<BH, 256>>>();
    k_kvpart2<<<dim3(NCH, BH), 256, KVP_SMEM>>>(value);  // profiled slot (idx 3)
    k_maxn<<<BH, 256>>>();
    k_hash<<<dim3(NTOK/256, BH), 256>>>(query, key, alpha, beta);
    k_sort<<<128, 512>>>();
    k_kvred<<<BH*MF*EH/256, 256>>>();
    k_qkv2<<<dim3(NTOK/128, BH), 256, QKV_SMEM>>>();
    k_bucket2<<<dim3(32, BH, 2), 256, BKT_SMEM>>>(query, key, value);
    k_mscal<<<dim3(NTOK/256, BH), 256>>>();
    k_final<<<NTOK*4/16, 256>>>(outW, outb, out);
}

// round 13
// speedup vs baseline: 1.0272x; 1.0272x over previous
#include <cuda_runtime.h>
#include <math.h>

#define BH 32
#define NTOK 4096
#define EH 64
#define MF 128
#define DM 512
#define NCH 16
#define IST 132
#define FST 132
#define DST 132

#define SQRT_TEMP 0.35355339059327373f
#define TEMPF 0.125f
#define HALF_LOG_M 2.4260151319598084f
#define LN2F 0.6931471805599453f

typedef unsigned long long u64t;
__device__ __forceinline__ u64t splat2(float x) {
    u64t r; asm("mov.b64 %0, {%1, %1};" : "=l"(r) : "f"(x)); return r;
}
__device__ __forceinline__ u64t pack2(float x, float y) {
    u64t r; asm("mov.b64 %0, {%1, %2};" : "=l"(r) : "f"(x), "f"(y)); return r;
}
__device__ __forceinline__ void fma2(u64t& c, u64t a, u64t b) {
    asm("fma.rn.f32x2 %0, %1, %2, %0;" : "+l"(c) : "l"(a), "l"(b));
}
__device__ __forceinline__ float2 unpk(u64t v) {
    float2 f; asm("mov.b64 {%0, %1}, %2;" : "=f"(f.x), "=f"(f.y) : "l"(v)); return f;
}

// ---------------- scratch ----------------
__device__ float g_q[BH*NTOK*EH];
__device__ float g_k[BH*NTOK*EH];
__device__ float g_v[BH*NTOK*EH];
__device__ float g_qn2[BH*NTOK];
__device__ float g_kn2[BH*NTOK];
__device__ float g_MQ2[BH];
__device__ float g_MK2[BH];
__device__ float g_hashq[2*BH*NTOK];
__device__ float g_hashk[2*BH*NTOK];
__device__ int   g_qpos[2*BH*NTOK];
__device__ int   g_kpos[2*BH*NTOK];
__device__ int   g_qrev[2*BH*NTOK];
__device__ int   g_krev[2*BH*NTOK];
__device__ float g_qp[(size_t)BH*NTOK*MF];
__device__ float g_kp[(size_t)BH*NTOK*MF];    // log-phi (pre-exp)
__device__ float g_qls[BH*NTOK];
__device__ float g_krm[BH*NTOK];
__device__ float g_kls[BH];
__device__ float g_kvp[(size_t)NCH*BH*MF*EH];
__device__ float g_ksp[NCH*BH*MF];
__device__ float g_kv[BH*MF*EH];
__device__ float g_ksum[BH*MF];
__device__ float g_qk1[BH*NTOK];
__device__ float g_qkv[(size_t)BH*NTOK*EH];
__device__ float g_ob[(size_t)2*BH*NTOK*EH];
__device__ float g_lseb[2*BH*NTOK];
__device__ float g_dsb[2*BH*NTOK];
__device__ float4 g_msc[BH*NTOK];

// ---------------- K1: split heads + squared norms ----------------
__global__ __launch_bounds__(256) void k_split(const float* __restrict__ query,
                                               const float* __restrict__ key,
                                               const float* __restrict__ value) {
    int tid = threadIdx.x;
    int tl = tid >> 6, e = tid & 63;
    int t = blockIdx.x*4 + tl, bh = blockIdx.y;
    int b = bh >> 3, hh = bh & 7;
    size_t gi = ((size_t)(b*NTOK + t))*DM + hh*EH + e;
    float qv = query[gi], kv = key[gi], vv = value[gi];
    size_t oi = ((size_t)bh*NTOK + t)*EH + e;
    g_q[oi] = qv; g_k[oi] = kv; g_v[oi] = vv;
    float q2 = qv*qv, k2 = kv*kv;
    #pragma unroll
    for (int o = 16; o; o >>= 1) {
        q2 += __shfl_down_sync(0xffffffffu, q2, o);
        k2 += __shfl_down_sync(0xffffffffu, k2, o);
    }
    __shared__ float sq[8], sk[8];
    if ((tid & 31) == 0) { sq[tid>>5] = q2; sk[tid>>5] = k2; }
    __syncthreads();
    if (e == 0) {
        g_qn2[bh*NTOK + t] = sq[2*tl] + sq[2*tl+1];
        g_kn2[bh*NTOK + t] = sk[2*tl] + sk[2*tl+1];
    }
}

// ---------------- K2: per-bh max squared norms ----------------
__global__ void k_maxn() {
    int bh = blockIdx.x, tid = threadIdx.x;
    float mq = 0.f, mk = 0.f;
    for (int i = tid; i < NTOK; i += 256) {
        mq = fmaxf(mq, g_qn2[bh*NTOK + i]);
        mk = fmaxf(mk, g_kn2[bh*NTOK + i]);
    }
    #pragma unroll
    for (int o = 16; o; o >>= 1) {
        mq = fmaxf(mq, __shfl_xor_sync(0xffffffffu, mq, o));
        mk = fmaxf(mk, __shfl_xor_sync(0xffffffffu, mk, o));
    }
    __shared__ float sq[8], sk[8];
    if ((tid & 31) == 0) { sq[tid>>5] = mq; sk[tid>>5] = mk; }
    __syncthreads();
    if (tid == 0) {
        float a = sq[0], b = sk[0];
        for (int w = 1; w < 8; w++) { a = fmaxf(a, sq[w]); b = fmaxf(b, sk[w]); }
        g_MQ2[bh] = a; g_MK2[bh] = b;
    }
}

// ---------------- K3: LSH hashes ----------------
__global__ void k_hash(const float* __restrict__ alpha, const float* __restrict__ beta) {
    __shared__ float sal[2*(EH+2)];
    __shared__ float sbe[2];
    int bh = blockIdx.y;
    int tid = threadIdx.x;
    if (tid < 2*(EH+2)) sal[tid] = alpha[tid];
    if (tid < 2) sbe[tid] = beta[tid];
    __syncthreads();
    int t = blockIdx.x*256 + tid;
    const float* qr = g_q + ((size_t)bh*NTOK + t)*EH;
    const float* kr = g_k + ((size_t)bh*NTOK + t)*EH;
    float a0 = 0.f, a1 = 0.f, c0 = 0.f, c1 = 0.f;
    #pragma unroll 8
    for (int e = 0; e < EH; e++) {
        float al0 = sal[e*2], al1 = sal[e*2+1];
        float qe = qr[e], ke = kr[e];
        a0 += qe*al0; a1 += qe*al1;
        c0 += ke*al0; c1 += ke*al1;
    }
    float S = g_MQ2[bh] + g_MK2[bh];
    float extq = sqrtf(fmaxf(S - g_qn2[bh*NTOK + t], 0.f));
    float extk = sqrtf(fmaxf(S - g_kn2[bh*NTOK + t], 0.f));
    g_hashq[bh*NTOK + t]           = a0 + extq*sal[EH*2]       + sbe[0];
    g_hashq[BH*NTOK + bh*NTOK + t] = a1 + extq*sal[EH*2+1]     + sbe[1];
    g_hashk[bh*NTOK + t]           = c0 + extk*sal[(EH+1)*2]   + sbe[0];
    g_hashk[BH*NTOK + bh*NTOK + t] = c1 + extk*sal[(EH+1)*2+1] + sbe[1];
}

// ---------------- K5: performer feature maps as tiled GEMM ----------------
#define FEATG_SMEM (2*64*FST*4 + 128*4)
__global__ __launch_bounds__(256, 2) void k_featg(const float* __restrict__ W) {
    extern __shared__ float sm[];
    float* sXt = sm;                    // [64][FST]
    float* sWt = sm + 64*FST;           // [64][FST]
    float* sN  = sm + 2*64*FST;         // [128]
    int nb = blockIdx.x, bh = blockIdx.y, isK = blockIdx.z;
    int tid = threadIdx.x, tx = tid & 15, ty = tid >> 4;
    const float* X  = isK ? g_k   : g_q;
    const float* n2 = isK ? g_kn2 : g_qn2;
    int tb = nb*128;
    for (int idx = tid; idx < 8192; idx += 256) {
        int i = idx >> 6, e = idx & 63;
        sXt[e*FST + i] = X[((size_t)bh*NTOK + tb + i)*EH + e];
        sWt[e*FST + i] = W[i*EH + e];
    }
    if (tid < 128) sN[tid] = n2[bh*NTOK + tb + tid];
    __syncthreads();
    u64t acc[4][8];
    #pragma unroll
    for (int r = 0; r < 4; r++)
        #pragma unroll
        for (int c = 0; c < 8; c++) acc[r][c] = 0ull;
    #pragma unroll 2
    for (int e = 0; e < 64; e++) {
        const u64t* ap = (const u64t*)(sXt + e*FST + ty*8);
        float4 b0q = *(const float4*)(sWt + e*FST + tx*8);
        float4 b1q = *(const float4*)(sWt + e*FST + tx*8 + 4);
        u64t bs[8];
        bs[0]=splat2(b0q.x); bs[1]=splat2(b0q.y); bs[2]=splat2(b0q.z); bs[3]=splat2(b0q.w);
        bs[4]=splat2(b1q.x); bs[5]=splat2(b1q.y); bs[6]=splat2(b1q.z); bs[7]=splat2(b1q.w);
        #pragma unroll
        for (int r2 = 0; r2 < 4; r2++) {
            u64t av = ap[r2];
            #pragma unroll
            for (int c = 0; c < 8; c++) fma2(acc[r2][c], av, bs[c]);
        }
    }
    #pragma unroll
    for (int r2 = 0; r2 < 4; r2++) {
        float2 v[8];
        #pragma unroll
        for (int c = 0; c < 8; c++) v[c] = unpk(acc[r2][c]);
        #pragma unroll
        for (int half = 0; half < 2; half++) {
            int row = ty*8 + r2*2 + half;
            int t = tb + row;
            float nn = 0.5f*TEMPF*sN[row] + HALF_LOG_M;
            float lp[8];
            float rm = -1e30f;
            #pragma unroll
            for (int c = 0; c < 8; c++) {
                lp[c] = (half ? v[c].y : v[c].x)*SQRT_TEMP - nn;
                rm = fmaxf(rm, lp[c]);
            }
            #pragma unroll
            for (int off = 8; off; off >>= 1) rm = fmaxf(rm, __shfl_xor_sync(0xffffffffu, rm, off));
            size_t base = ((size_t)bh*NTOK + t)*MF + tx*8;
            if (!isK) {
                *(float4*)(g_qp + base) = make_float4(__expf(lp[0]-rm), __expf(lp[1]-rm),
                                                      __expf(lp[2]-rm), __expf(lp[3]-rm));
                *(float4*)(g_qp + base + 4) = make_float4(__expf(lp[4]-rm), __expf(lp[5]-rm),
                                                          __expf(lp[6]-rm), __expf(lp[7]-rm));
                if (tx == 0) g_qls[bh*NTOK + t] = rm;
            } else {
                *(float4*)(g_kp + base)     = make_float4(lp[0], lp[1], lp[2], lp[3]);
                *(float4*)(g_kp + base + 4) = make_float4(lp[4], lp[5], lp[6], lp[7]);
                if (tx == 0) g_krm[bh*NTOK + t] = rm;
            }
        }
    }
}

// ---------------- K4: stable bitonic argsort ----------------
__global__ void k_sort() {
    __shared__ float sv[NTOK];
    __shared__ int   si[NTOK];
    int which = blockIdx.x >> 6;
    int rem   = blockIdx.x & 63;
    const float* src = which ? (g_hashk + (size_t)rem*NTOK) : (g_hashq + (size_t)rem*NTOK);
    int tid = threadIdx.x;
    for (int i = tid; i < NTOK; i += 512) { sv[i] = src[i]; si[i] = i; }
    __syncthreads();
    for (int k = 2; k <= NTOK; k <<= 1)
        for (int j = k >> 1; j > 0; j >>= 1) {
            for (int p = tid; p < NTOK/2; p += 512) {
                int i  = ((p & ~(j-1)) << 1) | (p & (j-1));
                int ix = i | j;
                bool up = ((i & k) == 0);
                float vi = sv[i], vj = sv[ix];
                int ii = si[i], ij = si[ix];
                bool agt = (vi > vj) || (vi == vj && ii > ij);
                if (agt == up) { sv[i] = vj; sv[ix] = vi; si[i] = ij; si[ix] = ii; }
            }
            __syncthreads();
        }
    int* pos = which ? g_kpos : g_qpos;
    int* rev = which ? g_krev : g_qrev;
    for (int r = tid; r < NTOK; r += 512) {
        int idx = si[r];
        pos[rem*NTOK + r]   = idx;
        rev[rem*NTOK + idx] = r;
    }
}

// ---------------- K6: per-bh max of k log-phi ----------------
__global__ void k_kls() {
    int bh = blockIdx.x, tid = threadIdx.x;
    float m = -1e30f;
    for (int i = tid; i < NTOK; i += 256) m = fmaxf(m, g_krm[bh*NTOK + i]);
    #pragma unroll
    for (int o = 16; o; o >>= 1) m = fmaxf(m, __shfl_xor_sync(0xffffffffu, m, o));
    __shared__ float s[8];
    if ((tid & 31) == 0) s[tid>>5] = m;
    __syncthreads();
    if (tid == 0) {
        float r = s[0];
        for (int w = 1; w < 8; w++) r = fmaxf(r, s[w]);
        g_kls[bh] = r;
    }
}

// ---------------- K8: partial kv = exp(k')^T v (2 tiles per block) ----------------
#define KVP_SMEM (128*IST*4 + 128*68*4)
__global__ __launch_bounds__(256, 2) void k_kvpart2() {
    extern __shared__ float sm[];
    float* sKP = sm;                    // [128 t][IST]
    float* sV  = sm + 128*IST;          // [128 t][68]
    int ch = blockIdx.x, bh = blockIdx.y;
    int tid = threadIdx.x, tx = tid & 15, ty = tid >> 4;
    float kls = g_kls[bh];
    u64t acc[4][4];
    #pragma unroll
    for (int r = 0; r < 4; r++)
        #pragma unroll
        for (int c = 0; c < 4; c++) acc[r][c] = 0ull;
    float csum = 0.f;
    for (int tile = 0; tile < 2; tile++) {
        int t0 = ch*256 + tile*128;
        __syncthreads();
        for (int idx = tid; idx < 16384; idx += 256) {
            int t = idx >> 7, m = idx & 127;
            sKP[t*IST + m] = __expf(g_kp[((size_t)bh*NTOK + t0 + t)*MF + m] - kls);
        }
        for (int idx = tid; idx < 8192; idx += 256) {
            int t = idx >> 6, d = idx & 63;
            sV[t*68 + d] = g_v[((size_t)bh*NTOK + t0 + t)*EH + d];
        }
        __syncthreads();
        #pragma unroll 4
        for (int t = 0; t < 128; t++) {
            const u64t* ap = (const u64t*)(sKP + t*IST + ty*8);
            float4 bq = *(const float4*)(sV + t*68 + tx*4);
            u64t b0 = splat2(bq.x), b1 = splat2(bq.y), b2 = splat2(bq.z), b3 = splat2(bq.w);
            #pragma unroll
            for (int r2 = 0; r2 < 4; r2++) {
                u64t av = ap[r2];
                fma2(acc[r2][0], av, b0); fma2(acc[r2][1], av, b1);
                fma2(acc[r2][2], av, b2); fma2(acc[r2][3], av, b3);
            }
        }
        if (tid < 128) {
            float s = 0.f;
            #pragma unroll 8
            for (int t = 0; t < 128; t++) s += sKP[t*IST + tid];
            csum += s;
        }
    }
    float* dst = g_kvp + ((size_t)(ch*BH + bh))*MF*EH;
    #pragma unroll
    for (int r2 = 0; r2 < 4; r2++) {
        float2 v0 = unpk(acc[r2][0]), v1 = unpk(acc[r2][1]);
        float2 v2 = unpk(acc[r2][2]), v3 = unpk(acc[r2][3]);
        int m = ty*8 + r2*2;
        *(float4*)(dst + (size_t)m*EH + tx*4)     = make_float4(v0.x, v1.x, v2.x, v3.x);
        *(float4*)(dst + (size_t)(m+1)*EH + tx*4) = make_float4(v0.y, v1.y, v2.y, v3.y);
    }
    if (tid < 128) g_ksp[(ch*BH + bh)*MF + tid] = csum;
}

// ---------------- K8b: deterministic reduce ----------------
__global__ void k_kvred() {
    int idx = blockIdx.x*256 + threadIdx.x;
    float s = 0.f;
    #pragma unroll
    for (int c = 0; c < NCH; c++) s += g_kvp[(size_t)c*BH*MF*EH + idx];
    g_kv[idx] = s;
    if (idx < BH*MF) {
        float ss = 0.f;
        #pragma unroll
        for (int c = 0; c < NCH; c++) ss += g_ksp[c*BH*MF + idx];
        g_ksum[idx] = ss;
    }
}

// ---------------- K9: qkv = q' kv + qk1, tiled GEMM ----------------
#define QKV_SMEM (128*IST*4 + 128*68*4 + 128*4)
__global__ __launch_bounds__(256, 2) void k_qkv2() {
    extern __shared__ float sm[];
    float* sQPt = sm;                   // [128 m][IST tokens]
    float* sKV  = sm + 128*IST;         // [128 m][68]
    float* sks  = sm + 128*IST + 128*68;
    int nb = blockIdx.x, bh = blockIdx.y;
    int tid = threadIdx.x, tx = tid & 15, ty = tid >> 4;
    int tb = nb*128;
    for (int idx = tid; idx < 16384; idx += 256) {
        int i = idx >> 7, m = idx & 127;
        sQPt[m*IST + i] = g_qp[((size_t)bh*NTOK + tb + i)*MF + m];
    }
    for (int idx = tid; idx < 8192; idx += 256) {
        int m = idx >> 6, d = idx & 63;
        sKV[m*68 + d] = g_kv[(size_t)bh*MF*EH + m*EH + d];
    }
    if (tid < 128) sks[tid] = g_ksum[bh*MF + tid];
    __syncthreads();
    u64t acc[4][4];
    #pragma unroll
    for (int r = 0; r < 4; r++)
        #pragma unroll
        for (int c = 0; c < 4; c++) acc[r][c] = 0ull;
    #pragma unroll 4
    for (int m = 0; m < 128; m++) {
        const u64t* ap = (const u64t*)(sQPt + m*IST + ty*8);
        float4 bq = *(const float4*)(sKV + m*68 + tx*4);
        u64t b0 = splat2(bq.x), b1 = splat2(bq.y), b2 = splat2(bq.z), b3 = splat2(bq.w);
        #pragma unroll
        for (int r2 = 0; r2 < 4; r2++) {
            u64t av = ap[r2];
            fma2(acc[r2][0], av, b0); fma2(acc[r2][1], av, b1);
            fma2(acc[r2][2], av, b2); fma2(acc[r2][3], av, b3);
        }
    }
    #pragma unroll
    for (int r2 = 0; r2 < 4; r2++) {
        float2 v0 = unpk(acc[r2][0]), v1 = unpk(acc[r2][1]);
        float2 v2 = unpk(acc[r2][2]), v3 = unpk(acc[r2][3]);
        int row = ty*8 + r2*2;
        *(float4*)(g_qkv + ((size_t)bh*NTOK + tb + row)*EH + tx*4)
            = make_float4(v0.x, v1.x, v2.x, v3.x);
        *(float4*)(g_qkv + ((size_t)bh*NTOK + tb + row + 1)*EH + tx*4)
            = make_float4(v0.y, v1.y, v2.y, v3.y);
    }
    if (tid < 128) {
        float s = 0.f;
        #pragma unroll 8
        for (int m = 0; m < 128; m++) s += sQPt[m*IST + tid]*sks[m];
        g_qk1[bh*NTOK + tb + tid] = s;
    }
}

// ======= K10: fully fused bucketed correction =======
#define R1_FLOATS 8704
#define BKT_SMEM ((128*DST + R1_FLOATS)*4)
__global__ __launch_bounds__(256, 2) void k_bucket2() {
    extern __shared__ float sm[];
    float* sD  = sm;                    // [128][DST]
    float* sR1 = sm + 128*DST;          // tiles: [32][IST] x2 ; later V [128][68]
    __shared__ int sQi[128], sKi[128], sQb[128], sKb[128];
    __shared__ float sPls[128];
    int nb = blockIdx.x, bh = blockIdx.y, h = blockIdx.z;
    int tid = threadIdx.x, tx = tid & 15, ty = tid >> 4;
    int o = 1 - h;
    float kls = g_kls[bh];
    if (tid < 128) {
        int qi = g_qpos[(h*BH + bh)*NTOK + nb*128 + tid];
        int ki = g_kpos[(h*BH + bh)*NTOK + nb*128 + tid];
        sQi[tid] = qi; sKi[tid] = ki;
        sQb[tid] = g_qrev[(o*BH + bh)*NTOK + qi] >> 7;
        sKb[tid] = g_krev[(o*BH + bh)*NTOK + ki] >> 7;
        sPls[tid] = g_qls[bh*NTOK + qi] + kls;
    }
    float* sQt = sR1;                   // [32][IST]
    float* sKt = sR1 + 32*IST;

    u64t aI[4][8];
    #pragma unroll
    for (int r = 0; r < 4; r++)
        #pragma unroll
        for (int c = 0; c < 8; c++) aI[r][c] = 0ull;
    for (int ec = 0; ec < 2; ec++) {
        __syncthreads();
        for (int idx = tid; idx < 4096; idx += 256) {
            int i = idx >> 5, el = idx & 31;
            sQt[el*IST + i] = g_q[((size_t)bh*NTOK + sQi[i])*EH + ec*32 + el];
            sKt[el*IST + i] = g_k[((size_t)bh*NTOK + sKi[i])*EH + ec*32 + el];
        }
        __syncthreads();
        #pragma unroll 2
        for (int e = 0; e < 32; e++) {
            const u64t* ap = (const u64t*)(sQt + e*IST + ty*8);
            float4 b0q = *(const float4*)(sKt + e*IST + tx*8);
            float4 b1q = *(const float4*)(sKt + e*IST + tx*8 + 4);
            u64t bs[8];
            bs[0]=splat2(b0q.x); bs[1]=splat2(b0q.y); bs[2]=splat2(b0q.z); bs[3]=splat2(b0q.w);
            bs[4]=splat2(b1q.x); bs[5]=splat2(b1q.y); bs[6]=splat2(b1q.z); bs[7]=splat2(b1q.w);
            #pragma unroll
            for (int r2 = 0; r2 < 4; r2++) {
                u64t av = ap[r2];
                #pragma unroll
                for (int c = 0; c < 8; c++) fma2(aI[r2][c], av, bs[c]);
            }
        }
    }
    #pragma unroll
    for (int r2 = 0; r2 < 4; r2++) {
        float2 v[8];
        #pragma unroll
        for (int c = 0; c < 8; c++) v[c] = unpk(aI[r2][c]);
        int row = ty*8 + r2*2;
        *(float4*)(sD + row*DST + tx*8)     = make_float4(v[0].x, v[1].x, v[2].x, v[3].x);
        *(float4*)(sD + row*DST + tx*8 + 4) = make_float4(v[4].x, v[5].x, v[6].x, v[7].x);
        *(float4*)(sD + (row+1)*DST + tx*8)     = make_float4(v[0].y, v[1].y, v[2].y, v[3].y);
        *(float4*)(sD + (row+1)*DST + tx*8 + 4) = make_float4(v[4].y, v[5].y, v[6].y, v[7].y);
    }

    u64t aP[4][8];
    #pragma unroll
    for (int r = 0; r < 4; r++)
        #pragma unroll
        for (int c = 0; c < 8; c++) aP[r][c] = 0ull;
    for (int mc = 0; mc < 4; mc++) {
        __syncthreads();
        for (int idx = tid; idx < 4096; idx += 256) {
            int i = idx >> 5, ml = idx & 31;
            sQt[ml*IST + i] = g_qp[((size_t)bh*NTOK + sQi[i])*MF + mc*32 + ml];
            sKt[ml*IST + i] = __expf(g_kp[((size_t)bh*NTOK + sKi[i])*MF + mc*32 + ml] - kls);
        }
        __syncthreads();
        #pragma unroll 2
        for (int m = 0; m < 32; m++) {
            const u64t* ap = (const u64t*)(sQt + m*IST + ty*8);
            float4 b0q = *(const float4*)(sKt + m*IST + tx*8);
            float4 b1q = *(const float4*)(sKt + m*IST + tx*8 + 4);
            u64t bs[8];
            bs[0]=splat2(b0q.x); bs[1]=splat2(b0q.y); bs[2]=splat2(b0q.z); bs[3]=splat2(b0q.w);
            bs[4]=splat2(b1q.x); bs[5]=splat2(b1q.y); bs[6]=splat2(b1q.z); bs[7]=splat2(b1q.w);
            #pragma unroll
            for (int r2 = 0; r2 < 4; r2++) {
                u64t av = ap[r2];
                #pragma unroll
                for (int c = 0; c < 8; c++) fma2(aP[r2][c], av, bs[c]);
            }
        }
    }
    __syncthreads();

    int kb[8];
    #pragma unroll
    for (int c = 0; c < 8; c++) kb[c] = sKb[tx*8 + c];
    #pragma unroll
    for (int r2 = 0; r2 < 4; r2++) {
        float2 P[8];
        #pragma unroll
        for (int c = 0; c < 8; c++) P[c] = unpk(aP[r2][c]);
        #pragma unroll
        for (int half = 0; half < 2; half++) {
            int row = ty*8 + r2*2 + half;
            int qb = sQb[row]; float pls = sPls[row];
            float4 in0 = *(const float4*)(sD + row*DST + tx*8);
            float4 in1 = *(const float4*)(sD + row*DST + tx*8 + 4);
            float iv[8] = {in0.x, in0.y, in0.z, in0.w, in1.x, in1.y, in1.z, in1.w};
            float pv[8];
            float rm = -1e30f;
            #pragma unroll
            for (int c = 0; c < 8; c++) {
                bool d2 = (qb == kb[c]);
                iv[c] = iv[c]*TEMPF - (d2 ? LN2F : 0.f);
                pv[c] = (half ? P[c].y : P[c].x) * (d2 ? 0.5f : 1.f);
                rm = fmaxf(rm, iv[c]);
            }
            #pragma unroll
            for (int off = 8; off; off >>= 1) rm = fmaxf(rm, __shfl_xor_sync(0xffffffffu, rm, off));
            float l = fmaxf(rm, pls);
            float pe = __expf(pls - l);
            float dv[8];
            float s = 0.f;
            #pragma unroll
            for (int c = 0; c < 8; c++) { dv[c] = __expf(iv[c] - l) - pv[c]*pe; s += dv[c]; }
            *(float4*)(sD + row*DST + tx*8)     = make_float4(dv[0], dv[1], dv[2], dv[3]);
            *(float4*)(sD + row*DST + tx*8 + 4) = make_float4(dv[4], dv[5], dv[6], dv[7]);
            #pragma unroll
            for (int off = 8; off; off >>= 1) s += __shfl_xor_sync(0xffffffffu, s, off);
            if (tx == 0) {
                int t = sQi[row];
                size_t bi = (size_t)(h*BH + bh)*NTOK + t;
                g_lseb[bi] = l;
                g_dsb[bi]  = s;
            }
        }
    }
    float* sV = sR1;                    // [128][68]
    for (int idx = tid; idx < 8192; idx += 256) {
        int i = idx >> 6, d = idx & 63;
        sV[i*68 + d] = g_v[((size_t)bh*NTOK + sKi[i])*EH + d];
    }
    __syncthreads();

    int tx2 = tid & 15, ty2 = tid >> 4;
    u64t accO[8][2];
    #pragma unroll
    for (int r = 0; r < 8; r++) { accO[r][0] = 0ull; accO[r][1] = 0ull; }
    for (int j0 = 0; j0 < 128; j0 += 4) {
        float4 a[8];
        #pragma unroll
        for (int r = 0; r < 8; r++) a[r] = *(const float4*)(sD + (ty2*8 + r)*DST + j0);
        #pragma unroll
        for (int jj = 0; jj < 4; jj++) {
            float4 t = *(const float4*)(sV + (j0 + jj)*68 + tx2*4);
            u64t bv0 = pack2(t.x, t.y), bv1 = pack2(t.z, t.w);
            #pragma unroll
            for (int r = 0; r < 8; r++) {
                float av = (jj==0)?a[r].x:(jj==1)?a[r].y:(jj==2)?a[r].z:a[r].w;
                u64t s = splat2(av);
                fma2(accO[r][0], s, bv0); fma2(accO[r][1], s, bv1);
            }
        }
    }
    #pragma unroll
    for (int r = 0; r < 8; r++) {
        int t = sQi[ty2*8 + r];
        float2 u0 = unpk(accO[r][0]), u1 = unpk(accO[r][1]);
        *(float4*)(g_ob + ((size_t)(h*BH + bh)*NTOK + t)*EH + tx2*4) =
            make_float4(u0.x, u0.y, u1.x, u1.y);
    }
}

// ---------------- K11: merge scalars per (bh, t) ----------------
__global__ void k_mscal() {
    int t = blockIdx.x*256 + threadIdx.x;
    int bh = blockIdx.y;
    size_t i0 = (size_t)bh*NTOK + t;
    size_t i1 = (size_t)(BH + bh)*NTOK + t;
    float l0 = g_lseb[i0], l1 = g_lseb[i1];
    float mx = fmaxf(l0, l1);
    float norm = mx + logf(__expf(l0 - mx) + __expf(l1 - mx));
    float p0 = __expf(l0 - norm), p1 = __expf(l1 - norm);
    float pls = g_qls[bh*NTOK + t] + g_kls[bh];
    float psc = __expf(pls - norm);
    float z = g_dsb[i0]*p0 + g_dsb[i1]*p1 + g_qk1[bh*NTOK + t]*psc;
    float invz = 1.f / fmaxf(z, 1e-6f);
    g_msc[i0] = make_float4(p0*invz, p1*invz, psc*invz, 0.f);
}

// ---------------- K12: final projection with fused merge ----------------
#define WS 130
#define XS 132
__global__ __launch_bounds__(256) void k_final(const float* __restrict__ Wf,
                                               const float* __restrict__ bias,
                                               float* __restrict__ out) {
    __shared__ float sW2[64*WS];
    __shared__ float sX[16*XS];
    int tid = threadIdx.x;
    int tok = tid >> 6, eo = tid & 63;
    int g0 = blockIdx.x*16;
    u64t acc2[4];
    #pragma unroll
    for (int tt = 0; tt < 4; tt++) acc2[tt] = 0ull;
    for (int c = 0; c < 4; c++) {
        __syncthreads();
        for (int idx = tid; idx < 8192; idx += 256) {
            int e2 = idx >> 7, hd = idx & 127;
            sW2[e2*WS + hd] = Wf[e2*512 + c*128 + hd];
        }
        for (int idx = tid; idx < 2048; idx += 256) {
            int tk = idx >> 7, hd = idx & 127;
            int gg = g0 + tk;
            int b = gg >> 12, t = gg & 4095;
            int hdg = c*128 + hd;
            int bh = b*8 + (hdg >> 6);
            int d = hdg & 63;
            size_t ti = (size_t)bh*NTOK + t;
            float4 ms = g_msc[ti];
            float val = g_ob[ti*EH + d]*ms.x
                      + g_ob[(size_t)BH*NTOK*EH + ti*EH + d]*ms.y
                      + g_qkv[ti*EH + d]*ms.z;
            sX[tk*XS + hd] = val;
        }
        __syncthreads();
        const u64t* wp = (const u64t*)(sW2 + eo*WS);
        #pragma unroll
        for (int tt = 0; tt < 4; tt++) {
            const float4* x4 = (const float4*)(sX + (tok + tt*4)*XS);
            #pragma unroll
            for (int h4 = 0; h4 < 32; h4++) {
                float4 xv = x4[h4];
                fma2(acc2[tt], pack2(xv.x, xv.y), wp[2*h4]);
                fma2(acc2[tt], pack2(xv.z, xv.w), wp[2*h4+1]);
            }
        }
    }
    float bv = bias[eo];
    #pragma unroll
    for (int tt = 0; tt < 4; tt++) {
        float2 u = unpk(acc2[tt]);
        out[(size_t)(g0 + tok + tt*4)*EH + eo] = u.x + u.y + bv;
    }
}

// ---------------- launch: fork/join streams ----------------
extern "C" void kernel_launch(void* const* d_in, const int* in_sizes, int n_in,
                              void* d_out, int out_size) {
    const float* query = (const float*)d_in[0];
    const float* key   = (const float*)d_in[1];
    const float* value = (const float*)d_in[2];
    const float* projW = (const float*)d_in[3];
    const float* alpha = (const float*)d_in[4];
    const float* beta  = (const float*)d_in[5];
    const float* outW  = (const float*)d_in[6];
    const float* outb  = (const float*)d_in[7];
    float* out = (float*)d_out;

    cudaFuncSetAttribute(k_featg,   cudaFuncAttributeMaxDynamicSharedMemorySize, FEATG_SMEM);
    cudaFuncSetAttribute(k_kvpart2, cudaFuncAttributeMaxDynamicSharedMemorySize, KVP_SMEM);
    cudaFuncSetAttribute(k_qkv2,    cudaFuncAttributeMaxDynamicSharedMemorySize, QKV_SMEM);
    cudaFuncSetAttribute(k_bucket2, cudaFuncAttributeMaxDynamicSharedMemorySize, BKT_SMEM);

    cudaStream_t s2;
    cudaStreamCreate(&s2);
    cudaEvent_t e1, e2;
    cudaEventCreateWithFlags(&e1, cudaEventDisableTiming);
    cudaEventCreateWithFlags(&e2, cudaEventDisableTiming);

    // main chain (default stream)
    k_split<<<dim3(NTOK/4, BH), 256>>>(query, key, value);
    cudaEventRecord(e1, 0);
    k_featg<<<dim3(NTOK/128, BH, 2), 256, FEATG_SMEM>>>(projW);
    k_kls<<<BH, 256>>>();
    k_kvpart2<<<dim3(NCH, BH), 256, KVP_SMEM>>>();       // profiled slot
    k_kvred<<<BH*MF*EH/256, 256>>>();
    k_qkv2<<<dim3(NTOK/128, BH), 256, QKV_SMEM>>>();

    // side chain (s2): maxn -> hash -> sort, overlapped with main
    cudaStreamWaitEvent(s2, e1, 0);
    k_maxn<<<BH, 256, 0, s2>>>();
    k_hash<<<dim3(NTOK/256, BH), 256, 0, s2>>>(alpha, beta);
    k_sort<<<128, 512, 0, s2>>>();
    cudaEventRecord(e2, s2);

    // join: bucket2 needs sort results + featg/kls
    cudaStreamWaitEvent(0, e2, 0);
    k_bucket2<<<dim3(32, BH, 2), 256, BKT_SMEM>>>();
    k_mscal<<<dim3(NTOK/256, BH), 256>>>();
    k_final<<<NTOK*4/16, 256>>>(outW, outb, out);

    cudaEventDestroy(e1);
    cudaEventDestroy(e2);
    cudaStreamDestroy(s2);
}